// round 7
// baseline (speedup 1.0000x reference)
#include <cuda_runtime.h>
#include <cstdint>

// ---------------- problem constants ----------------
#define STEPS 4096
#define DATA  8192
#define EMBD  1024
#define HDIM  128
#define ODIM  12
#define NCTA  8
#define TPB   128

// ---------------- device scratch (no allocations allowed) ----------------
__device__ float g_Mt[(size_t)DATA * HDIM];     // fused weight Mt[d][i]  (4 MB)
__device__ float g_pre[(size_t)STEPS * HDIM];   // pre_i2h[t][i] + c_fused (2 MB)
__device__ float g_cf[HDIM];                    // fused bias

__device__ __forceinline__ float sigm(float x) { return 1.f / (1.f + __expf(-x)); }

#define CLUSTER_SYNC() do { \
  asm volatile("barrier.cluster.arrive.aligned;" ::: "memory"); \
  asm volatile("barrier.cluster.wait.aligned;"   ::: "memory"); } while (0)

// broadcast one float to the same smem offset in all 8 cluster CTAs
__device__ __forceinline__ void bcast8(float* p, float v) {
    uint32_t la = (uint32_t)__cvta_generic_to_shared(p);
    uint32_t vb = __float_as_uint(v);
#pragma unroll
    for (int rk = 0; rk < NCTA; rk++) {
        uint32_t ra;
        asm volatile("mapa.shared::cluster.u32 %0, %1, %2;" : "=r"(ra) : "r"(la), "r"(rk));
        asm volatile("st.shared::cluster.u32 [%0], %1;" :: "r"(ra), "r"(vb) : "memory");
    }
}

// NOTE: parameter names must not collide with float4 member tokens x/y/z/w
#define FMA4(W_, X_) do { a0 = fmaf((W_).x,(X_).x,a0); a1 = fmaf((W_).y,(X_).y,a1); \
                          a2 = fmaf((W_).z,(X_).z,a2); a3 = fmaf((W_).w,(X_).w,a3); } while (0)

// =====================================================================
// K0: c_fused[i] = b_i2h[i] + sum_e b_s2i[e] * W_i2h[i][e]
// =====================================================================
__global__ void k_cf(const float* __restrict__ b_s2i,
                     const float* __restrict__ Wi2h,
                     const float* __restrict__ b_i2h) {
    int i = threadIdx.x;  // 128 threads
    const float4* b4 = (const float4*)b_s2i;
    const float4* w4 = (const float4*)(Wi2h + (size_t)i * 1152);
    float a0 = 0, a1 = 0, a2 = 0, a3 = 0;
    for (int k = 0; k < EMBD / 4; k++) { float4 bv = b4[k], wv = w4[k]; FMA4(wv, bv); }
    g_cf[i] = b_i2h[i] + ((a0 + a1) + (a2 + a3));
}

// =====================================================================
// K1: Mt[d][i] = sum_e Ws2i[e][d] * Wi2h[i][e]     grid(32,8), 256 thr
// =====================================================================
__global__ void __launch_bounds__(256) k_mt(const float* __restrict__ Ws2i,
                                            const float* __restrict__ Wi2h) {
    __shared__ float we[16][128];
    int d  = blockIdx.x * 256 + threadIdx.x;
    int i0 = blockIdx.y * 16;
    float acc[16];
#pragma unroll
    for (int ii = 0; ii < 16; ii++) acc[ii] = 0.f;
    for (int e0 = 0; e0 < EMBD; e0 += 128) {
#pragma unroll
        for (int k = 0; k < 8; k++) {
            int idx = k * 256 + threadIdx.x;
            int ii = idx >> 7, ee = idx & 127;
            we[ii][ee] = Wi2h[(size_t)(i0 + ii) * 1152 + e0 + ee];
        }
        __syncthreads();
        for (int ee = 0; ee < 128; ee++) {
            float ws = Ws2i[(size_t)(e0 + ee) * DATA + d];
#pragma unroll
            for (int ii = 0; ii < 16; ii++) acc[ii] = fmaf(we[ii][ee], ws, acc[ii]);
        }
        __syncthreads();
    }
#pragma unroll
    for (int ii = 0; ii < 16; ii++) g_Mt[(size_t)d * HDIM + i0 + ii] = acc[ii];
}

// =====================================================================
// K2: pre[t][i] = c_fused[i] + sum_d inputs[t][d] * Mt[d][i]
//     grid 256 blocks (16 t each), 256 thr
// =====================================================================
__global__ void __launch_bounds__(256) k_pre(const float* __restrict__ inputs) {
    __shared__ float xin[16 * 64];
    __shared__ float wm[64 * 128];
    int t0   = blockIdx.x * 16;
    int i    = threadIdx.x & 127;
    int trow = threadIdx.x >> 7;  // 0..1
    float acc[8];
#pragma unroll
    for (int k = 0; k < 8; k++) acc[k] = 0.f;
    for (int d0 = 0; d0 < DATA; d0 += 64) {
        {
            int idx = threadIdx.x * 4;
            int tt = idx >> 6, dd = idx & 63;
            *(float4*)&xin[idx] = *(const float4*)&inputs[(size_t)(t0 + tt) * DATA + d0 + dd];
        }
#pragma unroll
        for (int k = 0; k < 8; k++) {
            int x4 = (k * 256 + threadIdx.x) * 4;
            *(float4*)&wm[x4] = *(const float4*)&g_Mt[(size_t)d0 * HDIM + x4];
        }
        __syncthreads();
        for (int dd = 0; dd < 64; dd++) {
            float m = wm[dd * 128 + i];
#pragma unroll
            for (int tt = 0; tt < 8; tt++)
                acc[tt] = fmaf(xin[(trow + tt * 2) * 64 + dd], m, acc[tt]);
        }
        __syncthreads();
    }
    float cf = g_cf[i];
#pragma unroll
    for (int tt = 0; tt < 8; tt++)
        g_pre[(size_t)(t0 + trow + tt * 2) * HDIM + i] = acc[tt] + cf;
}

// =====================================================================
// K3: the sequential scan — 8-CTA cluster, 128 thr/CTA
// =====================================================================
#define OFF_L0W   0         /* 19*512  = 9728  */
#define OFF_L1W   9728      /* 16384 */
#define OFF_L2W   26112     /* 16384 */
#define OFF_WD    42496     /* 2048  */
#define OFF_WHH   44544     /* 2048  */
#define OFF_WO    46592     /* 1536  */
#define OFF_BG0   48128
#define OFF_BG1   48192
#define OFF_BG2   48256
#define OFF_BH2H  48320
#define OFF_BH2O  48336
#define OFF_H0    48352     /* 2*128 */
#define OFF_H1    48608
#define OFF_H2    48864
#define OFF_HD    49120     /* 128 */
#define OFF_HE    49248
#define OFF_HF    49376
#define OFF_OBUF  49504     /* 16 */
#define OFF_GTMP  49520     /* 64 */
#define OFF_CST   49584     /* 48 */
#define SMEM_FLOATS 49632
#define SMEM_BYTES  (SMEM_FLOATS * 4)

__device__ __forceinline__ void lstm_stage(const float* lw, const float* xnew,
                                           const float* hprev, const float* bg,
                                           float* cst, float* hdst, float* gtmp,
                                           int tid, int rank) {
    int half = tid & 1, rr = tid >> 1;
    const float4* W = (const float4*)lw;
    const float* xv = half ? hprev : xnew;
    float a0 = 0, a1 = 0, a2 = 0, a3 = 0;
#pragma unroll
    for (int k = 0; k < 32; k++) {
        float4 wv = W[(k << 7) + tid];
        float4 xq = *(const float4*)(xv + (k << 2));
        FMA4(wv, xq);
    }
    float acc = (a0 + a1) + (a2 + a3);
    acc += __shfl_xor_sync(0xffffffffu, acc, 1);
    if (!half) gtmp[rr] = acc + bg[rr];
    __syncthreads();
    if (tid < 16) {
        float gi = gtmp[tid], gf = gtmp[16 + tid], gg = gtmp[32 + tid], go = gtmp[48 + tid];
        float c = cst[tid];
        c = sigm(gf) * c + sigm(gi) * tanhf(gg);
        cst[tid] = c;
        float h = sigm(go) * tanhf(c);
        bcast8(hdst + rank * 16 + tid, h);
    }
}

__device__ __forceinline__ float head_dot16(const float* w, const float* xv, int tid) {
    int oct = tid & 7;
    const float4* W = (const float4*)w;
    float a0 = 0, a1 = 0, a2 = 0, a3 = 0;
#pragma unroll
    for (int c = 0; c < 4; c++) {
        float4 wv = W[(c << 7) + tid];
        float4 xq = *(const float4*)(xv + (oct << 4) + (c << 2));
        FMA4(wv, xq);
    }
    float acc = (a0 + a1) + (a2 + a3);
    acc += __shfl_xor_sync(0xffffffffu, acc, 4);
    acc += __shfl_xor_sync(0xffffffffu, acc, 2);
    acc += __shfl_xor_sync(0xffffffffu, acc, 1);
    return acc;
}

__global__ void __launch_bounds__(TPB, 1) __cluster_dims__(NCTA, 1, 1)
k_scan(const float* __restrict__ out0, const float* __restrict__ h0in,
       const float* __restrict__ c0in,
       const float* __restrict__ Wi2h, const float* __restrict__ Wh2h,
       const float* __restrict__ bh2h_g,
       const float* __restrict__ Wh2o, const float* __restrict__ bh2o_g,
       const float* __restrict__ Wih0, const float* __restrict__ Whh0,
       const float* __restrict__ bih0, const float* __restrict__ bhh0,
       const float* __restrict__ Wih1, const float* __restrict__ Whh1,
       const float* __restrict__ bih1, const float* __restrict__ bhh1,
       const float* __restrict__ Wih2, const float* __restrict__ Whh2,
       const float* __restrict__ bih2, const float* __restrict__ bhh2,
       float* __restrict__ dout, int out_size) {
    extern __shared__ float sm[];
    const int tid  = threadIdx.x;
    const int rank = blockIdx.x;  // grid == one 8-CTA cluster

    float* l0w  = sm + OFF_L0W;
    float* l1w  = sm + OFF_L1W;
    float* l2w  = sm + OFF_L2W;
    float* wd   = sm + OFF_WD;
    float* whh  = sm + OFF_WHH;
    float* wo   = sm + OFF_WO;
    float* bg0  = sm + OFF_BG0;
    float* bg1  = sm + OFF_BG1;
    float* bg2  = sm + OFF_BG2;
    float* bhh2h= sm + OFF_BH2H;
    float* bh2o = sm + OFF_BH2O;
    float* h0b  = sm + OFF_H0;
    float* h1b  = sm + OFF_H1;
    float* h2b  = sm + OFF_H2;
    float* hD   = sm + OFF_HD;
    float* hE   = sm + OFF_HE;
    float* hF   = sm + OFF_HF;
    float* obuf = sm + OFF_OBUF;
    float* gtmp = sm + OFF_GTMP;
    float* cst  = sm + OFF_CST;

    // ---------------- load weight slices (interleaved layouts) ----------------
    for (int idx = tid; idx < 16384; idx += TPB) {
        int k = idx >> 9, rem = idx & 511;
        int t = rem >> 2, c = rem & 3;
        int rr = t >> 1, half = t & 1;
        int R = (rr >> 4) * 128 + rank * 16 + (rr & 15);
        l1w[idx] = half ? Whh1[(size_t)R * 128 + k * 4 + c] : Wih1[(size_t)R * 128 + k * 4 + c];
        l2w[idx] = half ? Whh2[(size_t)R * 128 + k * 4 + c] : Wih2[(size_t)R * 128 + k * 4 + c];
    }
    for (int idx = tid; idx < 9728; idx += TPB) {
        int k = idx >> 9, rem = idx & 511;
        int t = rem >> 2, c = rem & 3;
        int rr = t >> 1, half = t & 1;
        int R = (rr >> 4) * 128 + rank * 16 + (rr & 15);
        float v;
        if (k < 16) v = Whh0[(size_t)R * 128 + half * 64 + k * 4 + c];
        else        v = half ? 0.f : Wih0[(size_t)R * 12 + (k - 16) * 4 + c];
        l0w[idx] = v;
    }
    for (int idx = tid; idx < 2048; idx += TPB) {
        int c = idx >> 9, rem = idx & 511;
        int t = rem >> 2, e = rem & 3;
        int r = t >> 3, oct = t & 7;
        wd[idx]  = Wi2h[(size_t)(rank * 16 + r) * 1152 + 1024 + oct * 16 + c * 4 + e];
        whh[idx] = Wh2h[(size_t)(rank * 16 + r) * 128 + oct * 16 + c * 4 + e];
    }
    for (int idx = tid; idx < 1536; idx += TPB) {
        int c = idx / 384, rem = idx % 384;
        int t = rem >> 2, e = rem & 3;
        int r = t >> 3, oct = t & 7;
        wo[idx] = Wh2o[(size_t)r * 128 + oct * 16 + c * 4 + e];
    }
    if (tid < 64) {
        int R = (tid >> 4) * 128 + rank * 16 + (tid & 15);
        bg0[tid] = bih0[R] + bhh0[R];
        bg1[tid] = bih1[R] + bhh1[R];
        bg2[tid] = bih2[R] + bhh2[R];
    }
    if (tid < 16) bhh2h[tid] = bh2h_g[rank * 16 + tid];
    if (tid < 12) { bh2o[tid] = bh2o_g[tid]; obuf[tid] = out0[tid]; }
    if (tid >= 12 && tid < 16) obuf[tid] = 0.f;
    if (tid < 48) {
        int l = tid >> 4, j = tid & 15;
        cst[tid] = c0in[l * 128 + rank * 16 + j];
    }
    h0b[128 + tid] = h0in[tid];
    h1b[128 + tid] = h0in[128 + tid];
    h2b[128 + tid] = h0in[256 + tid];
    __syncthreads();
    CLUSTER_SYNC();

    // ---------------- main scan ----------------
#pragma unroll 1
    for (int t = 0; t < STEPS; t++) {
        const int p = t & 1, q = p ^ 1;
        float* h0w = h0b + p * 128; const float* h0r = h0b + q * 128;
        float* h1w = h1b + p * 128; const float* h1r = h1b + q * 128;
        float* h2w = h2b + p * 128; const float* h2r = h2b + q * 128;

        float pre_r = 0.f;
        if ((tid & 7) == 0)
            pre_r = g_pre[(size_t)t * HDIM + rank * 16 + (tid >> 3)];

        // ---- stage A: LSTM layer 0 (x = previous output, 12-dim) ----
        {
            int half = tid & 1, rr = tid >> 1;
            const float4* W = (const float4*)l0w;
            const float* hv = h0r + half * 64;
            float a0 = 0, a1 = 0, a2 = 0, a3 = 0;
#pragma unroll
            for (int k = 0; k < 16; k++) {
                float4 wv = W[(k << 7) + tid];
                float4 xq = *(const float4*)(hv + (k << 2));
                FMA4(wv, xq);
            }
            if (!half) {
#pragma unroll
                for (int k = 0; k < 3; k++) {
                    float4 wv = W[((16 + k) << 7) + tid];
                    float4 xq = *(const float4*)(obuf + (k << 2));
                    FMA4(wv, xq);
                }
            }
            float acc = (a0 + a1) + (a2 + a3);
            acc += __shfl_xor_sync(0xffffffffu, acc, 1);
            if (!half) gtmp[rr] = acc + bg0[rr];
            __syncthreads();
            if (tid < 16) {
                float gi = gtmp[tid], gf = gtmp[16 + tid], gg = gtmp[32 + tid], go = gtmp[48 + tid];
                float c = cst[tid];
                c = sigm(gf) * c + sigm(gi) * tanhf(gg);
                cst[tid] = c;
                float h = sigm(go) * tanhf(c);
                bcast8(h0w + rank * 16 + tid, h);
            }
        }
        CLUSTER_SYNC();

        // ---- stage B: LSTM layer 1 ----
        lstm_stage(l1w, h0w, h1r, bg1, cst + 16, h1w, gtmp, tid, rank);
        CLUSTER_SYNC();

        // ---- stage C: LSTM layer 2 ----
        lstm_stage(l2w, h1w, h2r, bg2, cst + 32, h2w, gtmp, tid, rank);
        CLUSTER_SYNC();

        // ---- stage D: hid = tanh(pre + Wi2h_h @ h2) ----
        {
            float acc = head_dot16(wd, h2w, tid);
            if ((tid & 7) == 0) {
                float hv = tanhf(acc + pre_r);
                bcast8(hD + rank * 16 + (tid >> 3), hv);
            }
        }
        CLUSTER_SYNC();

        // ---- stage E: hid = relu(Wh2h @ hid + b) ----
        {
            float acc = head_dot16(whh, hD, tid);
            if ((tid & 7) == 0) {
                int r = tid >> 3;
                float hv = fmaxf(acc + bhh2h[r], 0.f);
                bcast8(hE + rank * 16 + r, hv);
            }
        }
        CLUSTER_SYNC();

        // ---- stage F: second shared h2h ----
        {
            float acc = head_dot16(whh, hE, tid);
            if ((tid & 7) == 0) {
                int r = tid >> 3;
                float hv = fmaxf(acc + bhh2h[r], 0.f);
                bcast8(hF + rank * 16 + r, hv);
            }
        }
        CLUSTER_SYNC();

        // ---- stage G: o = sigmoid(Wh2o @ hid + b) — redundant per CTA ----
        if (tid < 96) {
            int oct = tid & 7, r = tid >> 3;
            const float4* W = (const float4*)wo;
            float a0 = 0, a1 = 0, a2 = 0, a3 = 0;
#pragma unroll
            for (int c = 0; c < 4; c++) {
                float4 wv = W[c * 96 + tid];
                float4 xq = *(const float4*)(hF + (oct << 4) + (c << 2));
                FMA4(wv, xq);
            }
            float acc = (a0 + a1) + (a2 + a3);
            acc += __shfl_xor_sync(0xffffffffu, acc, 4);
            acc += __shfl_xor_sync(0xffffffffu, acc, 2);
            acc += __shfl_xor_sync(0xffffffffu, acc, 1);
            if (oct == 0) {
                float ov = sigm(acc + bh2o[r]);
                obuf[r] = ov;
                if (rank == 0) dout[(size_t)t * ODIM + r] = ov;
            }
        }
        __syncthreads();
    }

    // ---------------- final hN / cN (if the output buffer includes them) ----------------
    if (out_size >= STEPS * ODIM + 6 * HDIM) {
        const int base = STEPS * ODIM;  // 49152
        if (rank == 0) {
            dout[base + tid]        = h0b[128 + tid];
            dout[base + 128 + tid]  = h1b[128 + tid];
            dout[base + 256 + tid]  = h2b[128 + tid];
        }
        if (tid < 48) {
            int l = tid >> 4, j = tid & 15;
            dout[base + 384 + l * 128 + rank * 16 + j] = cst[tid];
        }
    }
}

// =====================================================================
// launch
// =====================================================================
extern "C" void kernel_launch(void* const* d_in, const int* in_sizes, int n_in,
                              void* d_out, int out_size) {
    const float* inputs = (const float*)d_in[0];
    const float* out0   = (const float*)d_in[1];
    const float* h0in   = (const float*)d_in[2];
    const float* c0in   = (const float*)d_in[3];
    const float* W_s2i  = (const float*)d_in[4];
    const float* b_s2i  = (const float*)d_in[5];
    const float* W_i2h  = (const float*)d_in[6];
    const float* b_i2h  = (const float*)d_in[7];
    const float* W_h2h  = (const float*)d_in[8];
    const float* b_h2h  = (const float*)d_in[9];
    const float* W_h2o  = (const float*)d_in[10];
    const float* b_h2o  = (const float*)d_in[11];
    const float* Wih0   = (const float*)d_in[12];
    const float* Whh0   = (const float*)d_in[13];
    const float* bih0   = (const float*)d_in[14];
    const float* bhh0   = (const float*)d_in[15];
    const float* Wih1   = (const float*)d_in[16];
    const float* Whh1   = (const float*)d_in[17];
    const float* bih1   = (const float*)d_in[18];
    const float* bhh1   = (const float*)d_in[19];
    const float* Wih2   = (const float*)d_in[20];
    const float* Whh2   = (const float*)d_in[21];
    const float* bih2   = (const float*)d_in[22];
    const float* bhh2   = (const float*)d_in[23];
    float* dout = (float*)d_out;

    cudaFuncSetAttribute(k_scan, cudaFuncAttributeMaxDynamicSharedMemorySize, SMEM_BYTES);

    k_cf<<<1, 128>>>(b_s2i, W_i2h, b_i2h);
    k_mt<<<dim3(DATA / 256, HDIM / 16), 256>>>(W_s2i, W_i2h);
    k_pre<<<STEPS / 16, 256>>>(inputs);
    k_scan<<<NCTA, TPB, SMEM_BYTES>>>(out0, h0in, c0in,
                                      W_i2h, W_h2h, b_h2h, W_h2o, b_h2o,
                                      Wih0, Whh0, bih0, bhh0,
                                      Wih1, Whh1, bih1, bhh1,
                                      Wih2, Whh2, bih2, bhh2,
                                      dout, out_size);
}

// round 10
// speedup vs baseline: 1.3770x; 1.3770x over previous
#include <cuda_runtime.h>
#include <cstdint>

// ---------------- problem constants ----------------
#define STEPS 4096
#define DATA  8192
#define EMBD  1024
#define HDIM  128
#define ODIM  12
#define NCTA  8
#define TPB   128

// ---------------- device scratch (no allocations allowed) ----------------
__device__ float g_Mt[(size_t)DATA * HDIM];     // fused weight Mt[d][i]  (4 MB)
__device__ float g_pre[(size_t)STEPS * HDIM];   // pre_i2h[t][i] + c_fused (2 MB)
__device__ float g_cf[HDIM];                    // fused bias

__device__ __forceinline__ float tanha(float x) {
    float y; asm("tanh.approx.f32 %0, %1;" : "=f"(y) : "f"(x)); return y;
}
__device__ __forceinline__ float sigm(float x) { return 0.5f + 0.5f * tanha(0.5f * x); }

#define CLUSTER_ARRIVE() asm volatile("barrier.cluster.arrive.aligned;" ::: "memory")
#define CLUSTER_WAIT()   asm volatile("barrier.cluster.wait.aligned;"   ::: "memory")

// broadcast one float to the same smem offset in all 8 cluster CTAs
__device__ __forceinline__ void bcast8(float* p, float v) {
    uint32_t la = (uint32_t)__cvta_generic_to_shared(p);
    uint32_t vb = __float_as_uint(v);
#pragma unroll
    for (int rk = 0; rk < NCTA; rk++) {
        uint32_t ra;
        asm volatile("mapa.shared::cluster.u32 %0, %1, %2;" : "=r"(ra) : "r"(la), "r"(rk));
        asm volatile("st.shared::cluster.u32 [%0], %1;" :: "r"(ra), "r"(vb) : "memory");
    }
}

// NOTE: parameter names must not collide with float4 member tokens x/y/z/w
#define FMA4(W_, X_) do { a0 = fmaf((W_).x,(X_).x,a0); a1 = fmaf((W_).y,(X_).y,a1); \
                          a2 = fmaf((W_).z,(X_).z,a2); a3 = fmaf((W_).w,(X_).w,a3); } while (0)

// =====================================================================
// K0: c_fused[i] = b_i2h[i] + sum_e b_s2i[e] * W_i2h[i][e]
// =====================================================================
__global__ void k_cf(const float* __restrict__ b_s2i,
                     const float* __restrict__ Wi2h,
                     const float* __restrict__ b_i2h) {
    int i = threadIdx.x;  // 128 threads
    const float4* b4 = (const float4*)b_s2i;
    const float4* w4 = (const float4*)(Wi2h + (size_t)i * 1152);
    float a0 = 0, a1 = 0, a2 = 0, a3 = 0;
    for (int k = 0; k < EMBD / 4; k++) { float4 bv = b4[k], wv = w4[k]; FMA4(wv, bv); }
    g_cf[i] = b_i2h[i] + ((a0 + a1) + (a2 + a3));
}

// =====================================================================
// K1: Mt[d][i] = sum_e Ws2i[e][d] * Wi2h[i][e]     grid(32,8), 256 thr
// =====================================================================
__global__ void __launch_bounds__(256) k_mt(const float* __restrict__ Ws2i,
                                            const float* __restrict__ Wi2h) {
    __shared__ float we[16][128];
    int d  = blockIdx.x * 256 + threadIdx.x;
    int i0 = blockIdx.y * 16;
    float acc[16];
#pragma unroll
    for (int ii = 0; ii < 16; ii++) acc[ii] = 0.f;
    for (int e0 = 0; e0 < EMBD; e0 += 128) {
#pragma unroll
        for (int k = 0; k < 8; k++) {
            int idx = k * 256 + threadIdx.x;
            int ii = idx >> 7, ee = idx & 127;
            we[ii][ee] = Wi2h[(size_t)(i0 + ii) * 1152 + e0 + ee];
        }
        __syncthreads();
        for (int ee = 0; ee < 128; ee++) {
            float ws = Ws2i[(size_t)(e0 + ee) * DATA + d];
#pragma unroll
            for (int ii = 0; ii < 16; ii++) acc[ii] = fmaf(we[ii][ee], ws, acc[ii]);
        }
        __syncthreads();
    }
#pragma unroll
    for (int ii = 0; ii < 16; ii++) g_Mt[(size_t)d * HDIM + i0 + ii] = acc[ii];
}

// =====================================================================
// K2: pre[t][i] = c_fused[i] + sum_d inputs[t][d] * Mt[d][i]
// =====================================================================
__global__ void __launch_bounds__(256) k_pre(const float* __restrict__ inputs) {
    __shared__ float xin[16 * 64];
    __shared__ float wm[64 * 128];
    int t0   = blockIdx.x * 16;
    int i    = threadIdx.x & 127;
    int trow = threadIdx.x >> 7;  // 0..1
    float acc[8];
#pragma unroll
    for (int k = 0; k < 8; k++) acc[k] = 0.f;
    for (int d0 = 0; d0 < DATA; d0 += 64) {
        {
            int idx = threadIdx.x * 4;
            int tt = idx >> 6, dd = idx & 63;
            *(float4*)&xin[idx] = *(const float4*)&inputs[(size_t)(t0 + tt) * DATA + d0 + dd];
        }
#pragma unroll
        for (int k = 0; k < 8; k++) {
            int x4 = (k * 256 + threadIdx.x) * 4;
            *(float4*)&wm[x4] = *(const float4*)&g_Mt[(size_t)d0 * HDIM + x4];
        }
        __syncthreads();
        for (int dd = 0; dd < 64; dd++) {
            float m = wm[dd * 128 + i];
#pragma unroll
            for (int tt = 0; tt < 8; tt++)
                acc[tt] = fmaf(xin[(trow + tt * 2) * 64 + dd], m, acc[tt]);
        }
        __syncthreads();
    }
    float cf = g_cf[i];
#pragma unroll
    for (int tt = 0; tt < 8; tt++)
        g_pre[(size_t)(t0 + trow + tt * 2) * HDIM + i] = acc[tt] + cf;
}

// =====================================================================
// K3: the sequential scan — 8-CTA cluster, 128 thr/CTA
//
// Thread map (LSTM stages): j = tid>>3 (h-index 0..15 of this CTA's slice),
//   g = (tid>>1)&3 (gate), cs = tid&1 (column half).
// LSTM weight layout: lw[((p*16+k)*128 + t)*4 + c], p=0:ih p=1:hh,
//   col = cs*64 + k*4 + c, row R = g*128 + rank*16 + j.
// Head D: thread t: row r = tid>>3, oct = tid&7 (16 cols each).
// E/F: full W_h2h row per thread held in REGISTERS (loaded once).
// =====================================================================
#define OFF_L0W   0         /* 9728  */
#define OFF_L1W   9728      /* 16384 */
#define OFF_L2W   26112     /* 16384 */
#define OFF_WD    42496     /* 2048  */
#define OFF_BHH   44544     /* 128   */
#define OFF_BH2O  44672     /* 16    */
#define OFF_H0    44688     /* 256   */
#define OFF_H1    44944     /* 256   */
#define OFF_H2    45200     /* 256   */
#define OFF_HD    45456     /* 128   */
#define OFF_HE    45584     /* 128   */
#define OFF_HF    45712     /* 128   */
#define OFF_OBUF  45840     /* 16    */
#define SMEM_FLOATS 45856
#define SMEM_BYTES  (SMEM_FLOATS * 4)

__global__ void __launch_bounds__(TPB, 1) __cluster_dims__(NCTA, 1, 1)
k_scan(const float* __restrict__ out0, const float* __restrict__ h0in,
       const float* __restrict__ c0in,
       const float* __restrict__ Wi2h, const float* __restrict__ Wh2h,
       const float* __restrict__ bh2h_g,
       const float* __restrict__ Wh2o, const float* __restrict__ bh2o_g,
       const float* __restrict__ Wih0, const float* __restrict__ Whh0,
       const float* __restrict__ bih0, const float* __restrict__ bhh0,
       const float* __restrict__ Wih1, const float* __restrict__ Whh1,
       const float* __restrict__ bih1, const float* __restrict__ bhh1,
       const float* __restrict__ Wih2, const float* __restrict__ Whh2,
       const float* __restrict__ bih2, const float* __restrict__ bhh2,
       float* __restrict__ dout, int out_size) {
    extern __shared__ float sm[];
    const int tid  = threadIdx.x;
    const int rank = blockIdx.x;
    const unsigned FULL = 0xffffffffu;

    float* l0w   = sm + OFF_L0W;
    float* l1w   = sm + OFF_L1W;
    float* l2w   = sm + OFF_L2W;
    float* wd    = sm + OFF_WD;
    float* bhhf  = sm + OFF_BHH;
    float* bh2o  = sm + OFF_BH2O;
    float* h0b   = sm + OFF_H0;
    float* h1b   = sm + OFF_H1;
    float* h2b   = sm + OFF_H2;
    float* hD    = sm + OFF_HD;
    float* hidE  = sm + OFF_HE;
    float* hidF  = sm + OFF_HF;
    float* obuf  = sm + OFF_OBUF;

    const int j   = tid >> 3;
    const int g   = (tid >> 1) & 3;
    const int cs  = tid & 1;
    const int oct = tid & 7;
    const int lane = tid & 31;
    const int base = lane & ~7;

    // ---------------- load LSTM weight slices ----------------
    for (int idx = tid; idx < 16384; idx += TPB) {
        int s = idx >> 9, rem = idx & 511;
        int t = rem >> 2, c = rem & 3;
        int p = s >> 4, k = s & 15;
        int jj = t >> 3, gg = (t >> 1) & 3, cc = t & 1;
        int R = gg * 128 + rank * 16 + jj;
        int col = cc * 64 + k * 4 + c;
        l1w[idx] = p ? Whh1[(size_t)R * 128 + col] : Wih1[(size_t)R * 128 + col];
        l2w[idx] = p ? Whh2[(size_t)R * 128 + col] : Wih2[(size_t)R * 128 + col];
    }
    for (int idx = tid; idx < 9728; idx += TPB) {
        int s = idx >> 9, rem = idx & 511;
        int t = rem >> 2, c = rem & 3;
        int jj = t >> 3, gg = (t >> 1) & 3, cc = t & 1;
        int R = gg * 128 + rank * 16 + jj;
        float v;
        if (s < 3) v = (cc == 0) ? Wih0[(size_t)R * 12 + s * 4 + c] : 0.f;
        else       v = Whh0[(size_t)R * 128 + cc * 64 + (s - 3) * 4 + c];
        l0w[idx] = v;
    }
    // head D weights (this CTA's 16 rows of Wi2h h-part)
    for (int idx = tid; idx < 2048; idx += TPB) {
        int c = idx >> 9, rem = idx & 511, t = rem >> 2, e = rem & 3;
        int r = t >> 3, oc = t & 7;
        wd[idx] = Wi2h[(size_t)(rank * 16 + r) * 1152 + 1024 + oc * 16 + c * 4 + e];
    }
    bhhf[tid] = bh2h_g[tid];
    if (tid < 12) { bh2o[tid] = bh2o_g[tid]; obuf[tid] = out0[tid]; }
    if (tid >= 12 && tid < 16) obuf[tid] = 0.f;
    h0b[128 + tid] = h0in[tid];
    h1b[128 + tid] = h0in[128 + tid];
    h2b[128 + tid] = h0in[256 + tid];

    // per-thread fused biases (only column-half 0 carries them)
    float bA = 0.f, bB = 0.f, bC = 0.f;
    {
        int R = g * 128 + rank * 16 + j;
        if (cs == 0) {
            bA = bih0[R] + bhh0[R];
            bB = bih1[R] + bhh1[R];
            bC = bih2[R] + bhh2[R];
        }
    }
    // cell state lives in gate-lane registers
    float cA = 0.f, cB = 0.f, cC = 0.f;
    if (oct == 0) {
        cA = c0in[0 * 128 + rank * 16 + j];
        cB = c0in[1 * 128 + rank * 16 + j];
        cC = c0in[2 * 128 + rank * 16 + j];
    }
    // E/F/G weights permanently in registers: thread t owns Wh2h row t (128 f)
    float4 wreg[32];
#pragma unroll
    for (int k = 0; k < 32; k++)
        wreg[k] = *(const float4*)&Wh2h[(size_t)tid * 128 + k * 4];
    float4 gwreg[4] = {};
    if (tid < 96) {
#pragma unroll
        for (int c = 0; c < 4; c++)
            gwreg[c] = *(const float4*)&Wh2o[(size_t)(tid >> 3) * 128 + oct * 16 + c * 4];
    }

    __syncthreads();
    CLUSTER_ARRIVE(); CLUSTER_WAIT();   // phase 0

    const float4* W0 = (const float4*)l0w;
    const float4* W1 = (const float4*)l1w;
    const float4* W2 = (const float4*)l2w;
    const float4* WD = (const float4*)wd;

    // ---------------- main scan ----------------
#pragma unroll 1
    for (int t = 0; t < STEPS; t++) {
        const int p = t & 1, q = p ^ 1;
        float* h0w = h0b + p * 128; const float* h0r = h0b + q * 128;
        float* h1w = h1b + p * 128; const float* h1r = h1b + q * 128;
        float* h2w = h2b + p * 128; const float* h2r = h2b + q * 128;

        float pre_r = 0.f;
        if (oct == 0) pre_r = g_pre[(size_t)t * HDIM + rank * 16 + j];

        // ======== stage A: LSTM layer 0 (x = previous 12-dim output) ========
        {
            const float4* hv = (const float4*)(h0r + cs * 64);
            float a0 = 0, a1 = 0, a2 = 0, a3 = 0;
#pragma unroll
            for (int k = 0; k < 16; k++) { float4 wv = W0[((3 + k) << 7) + tid]; FMA4(wv, hv[k]); }
            if (cs == 0) {
                const float4* ob4 = (const float4*)obuf;
#pragma unroll
                for (int k = 0; k < 3; k++) { float4 wv = W0[(k << 7) + tid]; FMA4(wv, ob4[k]); }
            }
            float acc = (a0 + a1) + (a2 + a3);
            acc += __shfl_xor_sync(FULL, acc, 1);
            acc += bA;
            float gf = __shfl_sync(FULL, acc, base + 2);
            float gg = __shfl_sync(FULL, acc, base + 4);
            float go = __shfl_sync(FULL, acc, base + 6);
            if (oct == 0) {
                cA = sigm(gf) * cA + sigm(acc) * tanha(gg);
                bcast8(h0w + rank * 16 + j, sigm(go) * tanha(cA));
            }
        }
        CLUSTER_ARRIVE();                       // phase A

        // ======== stage B: LSTM layer 1 — hh half hoisted over the barrier ====
        float a0 = 0, a1 = 0, a2 = 0, a3 = 0;
        {
            const float4* pv = (const float4*)(h1r + cs * 64);
#pragma unroll
            for (int k = 0; k < 16; k++) { float4 wv = W1[((16 + k) << 7) + tid]; FMA4(wv, pv[k]); }
        }
        CLUSTER_WAIT();                         // h0 new ready
        {
            const float4* xv = (const float4*)(h0w + cs * 64);
#pragma unroll
            for (int k = 0; k < 16; k++) { float4 wv = W1[(k << 7) + tid]; FMA4(wv, xv[k]); }
            float acc = (a0 + a1) + (a2 + a3);
            acc += __shfl_xor_sync(FULL, acc, 1);
            acc += bB;
            float gf = __shfl_sync(FULL, acc, base + 2);
            float gg = __shfl_sync(FULL, acc, base + 4);
            float go = __shfl_sync(FULL, acc, base + 6);
            if (oct == 0) {
                cB = sigm(gf) * cB + sigm(acc) * tanha(gg);
                bcast8(h1w + rank * 16 + j, sigm(go) * tanha(cB));
            }
        }
        CLUSTER_ARRIVE();                       // phase B

        // ======== stage C: LSTM layer 2 — hh half hoisted ========
        a0 = 0; a1 = 0; a2 = 0; a3 = 0;
        {
            const float4* pv = (const float4*)(h2r + cs * 64);
#pragma unroll
            for (int k = 0; k < 16; k++) { float4 wv = W2[((16 + k) << 7) + tid]; FMA4(wv, pv[k]); }
        }
        CLUSTER_WAIT();                         // h1 new ready
        {
            const float4* xv = (const float4*)(h1w + cs * 64);
#pragma unroll
            for (int k = 0; k < 16; k++) { float4 wv = W2[(k << 7) + tid]; FMA4(wv, xv[k]); }
            float acc = (a0 + a1) + (a2 + a3);
            acc += __shfl_xor_sync(FULL, acc, 1);
            acc += bC;
            float gf = __shfl_sync(FULL, acc, base + 2);
            float gg = __shfl_sync(FULL, acc, base + 4);
            float go = __shfl_sync(FULL, acc, base + 6);
            if (oct == 0) {
                cC = sigm(gf) * cC + sigm(acc) * tanha(gg);
                bcast8(h2w + rank * 16 + j, sigm(go) * tanha(cC));
            }
        }
        CLUSTER_ARRIVE();                       // phase C
        CLUSTER_WAIT();                         // h2 new ready

        // ======== stage D: hid = tanh(pre + Wi2h_h @ h2) — distributed ========
        {
            const float4* hx = (const float4*)(h2w + oct * 16);
            float d0 = 0, d1 = 0, d2 = 0, d3 = 0;
#pragma unroll
            for (int c = 0; c < 4; c++) {
                float4 wv = WD[(c << 7) + tid];
                d0 = fmaf(wv.x, hx[c].x, d0); d1 = fmaf(wv.y, hx[c].y, d1);
                d2 = fmaf(wv.z, hx[c].z, d2); d3 = fmaf(wv.w, hx[c].w, d3);
            }
            float acc = (d0 + d1) + (d2 + d3);
            acc += __shfl_xor_sync(FULL, acc, 1);
            acc += __shfl_xor_sync(FULL, acc, 2);
            acc += __shfl_xor_sync(FULL, acc, 4);
            if (oct == 0) bcast8(hD + rank * 16 + j, tanha(acc + pre_r));
        }
        CLUSTER_ARRIVE();                       // phase D
        CLUSTER_WAIT();                         // hD full ready

        // ======== stages E/F/G: redundant local (reg-resident weights) ========
        {
            const float4* xv = (const float4*)hD;
            float e0 = 0, e1 = 0, e2 = 0, e3 = 0;
#pragma unroll
            for (int k = 0; k < 32; k++) {
                e0 = fmaf(wreg[k].x, xv[k].x, e0); e1 = fmaf(wreg[k].y, xv[k].y, e1);
                e2 = fmaf(wreg[k].z, xv[k].z, e2); e3 = fmaf(wreg[k].w, xv[k].w, e3);
            }
            hidE[tid] = fmaxf(((e0 + e1) + (e2 + e3)) + bhhf[tid], 0.f);
        }
        __syncthreads();
        {
            const float4* xv = (const float4*)hidE;
            float e0 = 0, e1 = 0, e2 = 0, e3 = 0;
#pragma unroll
            for (int k = 0; k < 32; k++) {
                e0 = fmaf(wreg[k].x, xv[k].x, e0); e1 = fmaf(wreg[k].y, xv[k].y, e1);
                e2 = fmaf(wreg[k].z, xv[k].z, e2); e3 = fmaf(wreg[k].w, xv[k].w, e3);
            }
            hidF[tid] = fmaxf(((e0 + e1) + (e2 + e3)) + bhhf[tid], 0.f);
        }
        __syncthreads();
        if (tid < 96) {
            const float4* xv = (const float4*)(hidF + oct * 16);
            float e0 = 0, e1 = 0, e2 = 0, e3 = 0;
#pragma unroll
            for (int c = 0; c < 4; c++) {
                e0 = fmaf(gwreg[c].x, xv[c].x, e0); e1 = fmaf(gwreg[c].y, xv[c].y, e1);
                e2 = fmaf(gwreg[c].z, xv[c].z, e2); e3 = fmaf(gwreg[c].w, xv[c].w, e3);
            }
            float acc = (e0 + e1) + (e2 + e3);
            acc += __shfl_xor_sync(FULL, acc, 1);
            acc += __shfl_xor_sync(FULL, acc, 2);
            acc += __shfl_xor_sync(FULL, acc, 4);
            if (oct == 0) {
                int r = tid >> 3;  // 0..11
                float ov = sigm(acc + bh2o[r]);
                obuf[r] = ov;
                if (rank == 0) dout[(size_t)t * ODIM + r] = ov;
            }
        }
        __syncthreads();
    }

    // ---------------- final hN / cN ----------------
    if (out_size >= STEPS * ODIM + 6 * HDIM) {
        const int fb = STEPS * ODIM;  // 49152
        if (rank == 0) {
            dout[fb + tid]       = h0b[128 + tid];  // final parity = 1
            dout[fb + 128 + tid] = h1b[128 + tid];
            dout[fb + 256 + tid] = h2b[128 + tid];
        }
        if (oct == 0) {
            dout[fb + 384 + 0 * 128 + rank * 16 + j] = cA;
            dout[fb + 384 + 1 * 128 + rank * 16 + j] = cB;
            dout[fb + 384 + 2 * 128 + rank * 16 + j] = cC;
        }
    }
}

// =====================================================================
// launch
// =====================================================================
extern "C" void kernel_launch(void* const* d_in, const int* in_sizes, int n_in,
                              void* d_out, int out_size) {
    const float* inputs = (const float*)d_in[0];
    const float* out0   = (const float*)d_in[1];
    const float* h0in   = (const float*)d_in[2];
    const float* c0in   = (const float*)d_in[3];
    const float* W_s2i  = (const float*)d_in[4];
    const float* b_s2i  = (const float*)d_in[5];
    const float* W_i2h  = (const float*)d_in[6];
    const float* b_i2h  = (const float*)d_in[7];
    const float* W_h2h  = (const float*)d_in[8];
    const float* b_h2h  = (const float*)d_in[9];
    const float* W_h2o  = (const float*)d_in[10];
    const float* b_h2o  = (const float*)d_in[11];
    const float* Wih0   = (const float*)d_in[12];
    const float* Whh0   = (const float*)d_in[13];
    const float* bih0   = (const float*)d_in[14];
    const float* bhh0   = (const float*)d_in[15];
    const float* Wih1   = (const float*)d_in[16];
    const float* Whh1   = (const float*)d_in[17];
    const float* bih1   = (const float*)d_in[18];
    const float* bhh1   = (const float*)d_in[19];
    const float* Wih2   = (const float*)d_in[20];
    const float* Whh2   = (const float*)d_in[21];
    const float* bih2   = (const float*)d_in[22];
    const float* bhh2   = (const float*)d_in[23];
    float* dout = (float*)d_out;

    cudaFuncSetAttribute(k_scan, cudaFuncAttributeMaxDynamicSharedMemorySize, SMEM_BYTES);

    k_cf<<<1, 128>>>(b_s2i, W_i2h, b_i2h);
    k_mt<<<dim3(DATA / 256, HDIM / 16), 256>>>(W_s2i, W_i2h);
    k_pre<<<STEPS / 16, 256>>>(inputs);
    k_scan<<<NCTA, TPB, SMEM_BYTES>>>(out0, h0in, c0in,
                                      W_i2h, W_h2h, b_h2h, W_h2o, b_h2o,
                                      Wih0, Whh0, bih0, bhh0,
                                      Wih1, Whh1, bih1, bhh1,
                                      Wih2, Whh2, bih2, bhh2,
                                      dout, out_size);
}

// round 11
// speedup vs baseline: 1.8364x; 1.3336x over previous
#include <cuda_runtime.h>
#include <cstdint>

// ---------------- problem constants ----------------
#define STEPS 4096
#define DATA  8192
#define EMBD  1024
#define HDIM  128
#define ODIM  12
#define NCTA  8
#define TPB   128

// ---------------- device scratch (no allocations allowed) ----------------
__device__ float g_Mt[(size_t)DATA * HDIM];     // fused weight Mt[d][i]  (4 MB)
__device__ float g_pre[(size_t)STEPS * HDIM];   // pre_i2h[t][i] + c_fused (2 MB)
__device__ float g_cf[HDIM];                    // fused bias

__device__ __forceinline__ float tanha(float x) {
    float y; asm("tanh.approx.f32 %0, %1;" : "=f"(y) : "f"(x)); return y;
}
__device__ __forceinline__ float sigm(float x) { return 0.5f + 0.5f * tanha(0.5f * x); }

#define CLUSTER_SYNC() do { \
  asm volatile("barrier.cluster.arrive.aligned;" ::: "memory"); \
  asm volatile("barrier.cluster.wait.aligned;"   ::: "memory"); } while (0)

// NOTE: parameter names must not collide with float4 member tokens x/y/z/w
#define FMA4(W_, X_) do { a0 = fmaf((W_).x,(X_).x,a0); a1 = fmaf((W_).y,(X_).y,a1); \
                          a2 = fmaf((W_).z,(X_).z,a2); a3 = fmaf((W_).w,(X_).w,a3); } while (0)

// =====================================================================
// K0: c_fused[i] = b_i2h[i] + sum_e b_s2i[e] * W_i2h[i][e]
// =====================================================================
__global__ void k_cf(const float* __restrict__ b_s2i,
                     const float* __restrict__ Wi2h,
                     const float* __restrict__ b_i2h) {
    int i = threadIdx.x;  // 128 threads
    const float4* b4 = (const float4*)b_s2i;
    const float4* w4 = (const float4*)(Wi2h + (size_t)i * 1152);
    float a0 = 0, a1 = 0, a2 = 0, a3 = 0;
    for (int k = 0; k < EMBD / 4; k++) { float4 bv = b4[k], wv = w4[k]; FMA4(wv, bv); }
    g_cf[i] = b_i2h[i] + ((a0 + a1) + (a2 + a3));
}

// =====================================================================
// K1: Mt[d][i] = sum_e Ws2i[e][d] * Wi2h[i][e]     grid(32,8), 256 thr
// =====================================================================
__global__ void __launch_bounds__(256) k_mt(const float* __restrict__ Ws2i,
                                            const float* __restrict__ Wi2h) {
    __shared__ float we[16][128];
    int d  = blockIdx.x * 256 + threadIdx.x;
    int i0 = blockIdx.y * 16;
    float acc[16];
#pragma unroll
    for (int ii = 0; ii < 16; ii++) acc[ii] = 0.f;
    for (int e0 = 0; e0 < EMBD; e0 += 128) {
#pragma unroll
        for (int k = 0; k < 8; k++) {
            int idx = k * 256 + threadIdx.x;
            int ii = idx >> 7, ee = idx & 127;
            we[ii][ee] = Wi2h[(size_t)(i0 + ii) * 1152 + e0 + ee];
        }
        __syncthreads();
        for (int ee = 0; ee < 128; ee++) {
            float ws = Ws2i[(size_t)(e0 + ee) * DATA + d];
#pragma unroll
            for (int ii = 0; ii < 16; ii++) acc[ii] = fmaf(we[ii][ee], ws, acc[ii]);
        }
        __syncthreads();
    }
#pragma unroll
    for (int ii = 0; ii < 16; ii++) g_Mt[(size_t)d * HDIM + i0 + ii] = acc[ii];
}

// =====================================================================
// K2: pre[t][i] = c_fused[i] + sum_d inputs[t][d] * Mt[d][i]
// =====================================================================
__global__ void __launch_bounds__(256) k_pre(const float* __restrict__ inputs) {
    __shared__ float xin[16 * 64];
    __shared__ float wm[64 * 128];
    int t0   = blockIdx.x * 16;
    int i    = threadIdx.x & 127;
    int trow = threadIdx.x >> 7;  // 0..1
    float acc[8];
#pragma unroll
    for (int k = 0; k < 8; k++) acc[k] = 0.f;
    for (int d0 = 0; d0 < DATA; d0 += 64) {
        {
            int idx = threadIdx.x * 4;
            int tt = idx >> 6, dd = idx & 63;
            *(float4*)&xin[idx] = *(const float4*)&inputs[(size_t)(t0 + tt) * DATA + d0 + dd];
        }
#pragma unroll
        for (int k = 0; k < 8; k++) {
            int x4 = (k * 256 + threadIdx.x) * 4;
            *(float4*)&wm[x4] = *(const float4*)&g_Mt[(size_t)d0 * HDIM + x4];
        }
        __syncthreads();
        for (int dd = 0; dd < 64; dd++) {
            float m = wm[dd * 128 + i];
#pragma unroll
            for (int tt = 0; tt < 8; tt++)
                acc[tt] = fmaf(xin[(trow + tt * 2) * 64 + dd], m, acc[tt]);
        }
        __syncthreads();
    }
    float cf = g_cf[i];
#pragma unroll
    for (int tt = 0; tt < 8; tt++)
        g_pre[(size_t)(t0 + trow + tt * 2) * HDIM + i] = acc[tt] + cf;
}

// =====================================================================
// K3: the sequential scan — 8-CTA cluster, 128 thr/CTA, mbarrier p2p sync
// =====================================================================
#define OFF_L0W   0         /* 9728  */
#define OFF_L1W   9728      /* 16384 */
#define OFF_L2W   26112     /* 16384 */
#define OFF_WD    42496     /* 2048  */
#define OFF_BHH   44544     /* 128   */
#define OFF_BH2O  44672     /* 16    */
#define OFF_H0    44688     /* 256   */
#define OFF_H1    44944     /* 256   */
#define OFF_H2    45200     /* 256   */
#define OFF_HD    45456     /* 128   */
#define OFF_HE    45584     /* 128   */
#define OFF_HF    45712     /* 128   */
#define OFF_OBUF  45840     /* 16    */
#define OFF_MBAR  45856     /* 4 mbarriers = 8 floats (8B aligned) */
#define SMEM_FLOATS 45864
#define SMEM_BYTES  (SMEM_FLOATS * 4)

// barrier byte offsets (from smem base)
#define B_A ((OFF_MBAR + 0) * 4)
#define B_B ((OFF_MBAR + 2) * 4)
#define B_C ((OFF_MBAR + 4) * 4)
#define B_D ((OFF_MBAR + 6) * 4)

// store v into all 8 CTAs at byte offset doff, then arrive on each CTA's
// mbarrier at byte offset boff (release orders the store before the arrive)
__device__ __forceinline__ void bcast_arrive(const uint32_t* rb, uint32_t doff,
                                             float v, uint32_t boff) {
    uint32_t vb = __float_as_uint(v);
#pragma unroll
    for (int rk = 0; rk < NCTA; rk++)
        asm volatile("st.shared::cluster.u32 [%0], %1;" :: "r"(rb[rk] + doff), "r"(vb) : "memory");
#pragma unroll
    for (int rk = 0; rk < NCTA; rk++)
        asm volatile("mbarrier.arrive.shared::cluster.b64 _, [%0];" :: "r"(rb[rk] + boff) : "memory");
}

__device__ __forceinline__ void mbar_wait(uint32_t mbar, uint32_t ph) {
    asm volatile(
        "{\n\t"
        ".reg .pred P;\n\t"
        "WL_%=:\n\t"
        "mbarrier.try_wait.parity.acquire.cluster.shared::cta.b64 P, [%0], %1, 0x989680;\n\t"
        "@P bra.uni WD_%=;\n\t"
        "bra.uni WL_%=;\n\t"
        "WD_%=:\n\t"
        "}"
        :: "r"(mbar), "r"(ph) : "memory");
}

// gate tail: acc = (bias-included, half-combined) gate-i value in cs lanes
__device__ __forceinline__ void gate_tail(float acc, float& cX,
                                          const uint32_t* rb, uint32_t doff,
                                          uint32_t boff, int oct, int base) {
    const unsigned FULL = 0xffffffffu;
    float gf = __shfl_sync(FULL, acc, base + 2);
    float gg = __shfl_sync(FULL, acc, base + 4);
    float go = __shfl_sync(FULL, acc, base + 6);
    if (oct == 0) {
        cX = sigm(gf) * cX + sigm(acc) * tanha(gg);
        bcast_arrive(rb, doff, sigm(go) * tanha(cX), boff);
    }
}

__global__ void __launch_bounds__(TPB, 1) __cluster_dims__(NCTA, 1, 1)
k_scan(const float* __restrict__ out0, const float* __restrict__ h0in,
       const float* __restrict__ c0in,
       const float* __restrict__ Wi2h, const float* __restrict__ Wh2h,
       const float* __restrict__ bh2h_g,
       const float* __restrict__ Wh2o, const float* __restrict__ bh2o_g,
       const float* __restrict__ Wih0, const float* __restrict__ Whh0,
       const float* __restrict__ bih0, const float* __restrict__ bhh0,
       const float* __restrict__ Wih1, const float* __restrict__ Whh1,
       const float* __restrict__ bih1, const float* __restrict__ bhh1,
       const float* __restrict__ Wih2, const float* __restrict__ Whh2,
       const float* __restrict__ bih2, const float* __restrict__ bhh2,
       float* __restrict__ dout, int out_size) {
    extern __shared__ float sm[];
    const int tid  = threadIdx.x;
    const int rank = blockIdx.x;
    const unsigned FULL = 0xffffffffu;
    const uint32_t sbase = (uint32_t)__cvta_generic_to_shared(sm);

    float* l0w   = sm + OFF_L0W;
    float* l1w   = sm + OFF_L1W;
    float* l2w   = sm + OFF_L2W;
    float* wd    = sm + OFF_WD;
    float* bhhf  = sm + OFF_BHH;
    float* bh2o  = sm + OFF_BH2O;
    float* h0b   = sm + OFF_H0;
    float* h1b   = sm + OFF_H1;
    float* h2b   = sm + OFF_H2;
    float* hD    = sm + OFF_HD;
    float* hidE  = sm + OFF_HE;
    float* hidF  = sm + OFF_HF;
    float* obuf  = sm + OFF_OBUF;

    const int j   = tid >> 3;
    const int g   = (tid >> 1) & 3;
    const int cs  = tid & 1;
    const int oct = tid & 7;
    const int lane = tid & 31;
    const int base = lane & ~7;

    // remote smem base of every cluster CTA (mapa hoisted out of the loop)
    uint32_t rb[NCTA];
#pragma unroll
    for (int rk = 0; rk < NCTA; rk++)
        asm("mapa.shared::cluster.u32 %0, %1, %2;" : "=r"(rb[rk]) : "r"(sbase), "r"(rk));

    // mbarrier init (count = 16 producer lanes * 8 CTAs = 128)
    if (tid == 0) {
#pragma unroll
        for (int b = 0; b < 4; b++)
            asm volatile("mbarrier.init.shared.b64 [%0], %1;"
                         :: "r"(sbase + B_A + 8u * b), "r"(128) : "memory");
    }

    // ---------------- load LSTM weight slices ----------------
    for (int idx = tid; idx < 16384; idx += TPB) {
        int s = idx >> 9, rem = idx & 511;
        int t = rem >> 2, c = rem & 3;
        int p = s >> 4, k = s & 15;
        int jj = t >> 3, gg = (t >> 1) & 3, cc = t & 1;
        int R = gg * 128 + rank * 16 + jj;
        int col = cc * 64 + k * 4 + c;
        l1w[idx] = p ? Whh1[(size_t)R * 128 + col] : Wih1[(size_t)R * 128 + col];
        l2w[idx] = p ? Whh2[(size_t)R * 128 + col] : Wih2[(size_t)R * 128 + col];
    }
    for (int idx = tid; idx < 9728; idx += TPB) {
        int s = idx >> 9, rem = idx & 511;
        int t = rem >> 2, c = rem & 3;
        int jj = t >> 3, gg = (t >> 1) & 3, cc = t & 1;
        int R = gg * 128 + rank * 16 + jj;
        float v;
        if (s < 3) v = (cc == 0) ? Wih0[(size_t)R * 12 + s * 4 + c] : 0.f;
        else       v = Whh0[(size_t)R * 128 + cc * 64 + (s - 3) * 4 + c];
        l0w[idx] = v;
    }
    for (int idx = tid; idx < 2048; idx += TPB) {
        int c = idx >> 9, rem = idx & 511, t = rem >> 2, e = rem & 3;
        int r = t >> 3, oc = t & 7;
        wd[idx] = Wi2h[(size_t)(rank * 16 + r) * 1152 + 1024 + oc * 16 + c * 4 + e];
    }
    bhhf[tid] = bh2h_g[tid];
    if (tid < 12) { bh2o[tid] = bh2o_g[tid]; obuf[tid] = out0[tid]; }
    if (tid >= 12 && tid < 16) obuf[tid] = 0.f;
    h0b[128 + tid] = h0in[tid];
    h1b[128 + tid] = h0in[128 + tid];
    h2b[128 + tid] = h0in[256 + tid];

    float bA = 0.f, bB = 0.f, bC = 0.f;
    {
        int R = g * 128 + rank * 16 + j;
        if (cs == 0) {
            bA = bih0[R] + bhh0[R];
            bB = bih1[R] + bhh1[R];
            bC = bih2[R] + bhh2[R];
        }
    }
    float cA = 0.f, cB = 0.f, cC = 0.f;
    if (oct == 0) {
        cA = c0in[0 * 128 + rank * 16 + j];
        cB = c0in[1 * 128 + rank * 16 + j];
        cC = c0in[2 * 128 + rank * 16 + j];
    }
    // E/F/G weights permanently in registers
    float4 wreg[32];
#pragma unroll
    for (int k = 0; k < 32; k++)
        wreg[k] = *(const float4*)&Wh2h[(size_t)tid * 128 + k * 4];
    float4 gwreg[4] = {};
    if (tid < 96) {
#pragma unroll
        for (int c = 0; c < 4; c++)
            gwreg[c] = *(const float4*)&Wh2o[(size_t)(tid >> 3) * 128 + oct * 16 + c * 4];
    }

    __syncthreads();
    CLUSTER_SYNC();   // all SMEM init + mbarrier init visible cluster-wide

    const float4* W0 = (const float4*)l0w;
    const float4* W1 = (const float4*)l1w;
    const float4* W2 = (const float4*)l2w;
    const float4* WD = (const float4*)wd;

    // ---------------- prologue: stage A of step 0 ----------------
    {
        const float4* hv = (const float4*)(h0b + 128 + cs * 64);  // parity 1 init
        float a0 = 0, a1 = 0, a2 = 0, a3 = 0;
#pragma unroll
        for (int k = 0; k < 16; k++) { float4 wv = W0[((3 + k) << 7) + tid]; FMA4(wv, hv[k]); }
        if (cs == 0) {
            const float4* ob4 = (const float4*)obuf;
#pragma unroll
            for (int k = 0; k < 3; k++) { float4 wv = W0[(k << 7) + tid]; FMA4(wv, ob4[k]); }
        }
        float acc = (a0 + a1) + (a2 + a3);
        acc += __shfl_xor_sync(FULL, acc, 1);
        acc += bA;
        gate_tail(acc, cA, rb, (OFF_H0 + 0 + rank * 16 + j) * 4, B_A, oct, base);
    }

    // ---------------- main scan ----------------
#pragma unroll 1
    for (int t = 0; t < STEPS; t++) {
        const int p = t & 1, q = p ^ 1;
        const uint32_t ph = (uint32_t)(t & 1);
        float* h0w = h0b + p * 128;
        float* h1w = h1b + p * 128; const float* h1r = h1b + q * 128;
        float* h2w = h2b + p * 128; const float* h2r = h2b + q * 128;

        float pre_r = 0.f;
        if (oct == 0) pre_r = g_pre[(size_t)t * HDIM + rank * 16 + j];

        // ======== stage B: LSTM layer 1 — hh half hoisted over wait_A ========
        float a0 = 0, a1 = 0, a2 = 0, a3 = 0;
        {
            const float4* pv = (const float4*)(h1r + cs * 64);
#pragma unroll
            for (int k = 0; k < 16; k++) { float4 wv = W1[((16 + k) << 7) + tid]; FMA4(wv, pv[k]); }
        }
        mbar_wait(sbase + B_A, ph);             // h0(t) ready everywhere
        {
            const float4* xv = (const float4*)(h0w + cs * 64);
#pragma unroll
            for (int k = 0; k < 16; k++) { float4 wv = W1[(k << 7) + tid]; FMA4(wv, xv[k]); }
            float acc = (a0 + a1) + (a2 + a3);
            acc += __shfl_xor_sync(FULL, acc, 1);
            acc += bB;
            gate_tail(acc, cB, rb, (OFF_H1 + p * 128 + rank * 16 + j) * 4, B_B, oct, base);
        }

        // ======== stage C: LSTM layer 2 — hh half hoisted over wait_B ========
        a0 = 0; a1 = 0; a2 = 0; a3 = 0;
        {
            const float4* pv = (const float4*)(h2r + cs * 64);
#pragma unroll
            for (int k = 0; k < 16; k++) { float4 wv = W2[((16 + k) << 7) + tid]; FMA4(wv, pv[k]); }
        }
        mbar_wait(sbase + B_B, ph);             // h1(t) ready
        {
            const float4* xv = (const float4*)(h1w + cs * 64);
#pragma unroll
            for (int k = 0; k < 16; k++) { float4 wv = W2[(k << 7) + tid]; FMA4(wv, xv[k]); }
            float acc = (a0 + a1) + (a2 + a3);
            acc += __shfl_xor_sync(FULL, acc, 1);
            acc += bC;
            gate_tail(acc, cC, rb, (OFF_H2 + p * 128 + rank * 16 + j) * 4, B_C, oct, base);
        }
        mbar_wait(sbase + B_C, ph);             // h2(t) ready

        // ======== stage D: hid = tanh(pre + Wi2h_h @ h2) — distributed ========
        {
            const float4* hx = (const float4*)(h2w + oct * 16);
            float d0 = 0, d1 = 0, d2 = 0, d3 = 0;
#pragma unroll
            for (int c = 0; c < 4; c++) {
                float4 wv = WD[(c << 7) + tid];
                d0 = fmaf(wv.x, hx[c].x, d0); d1 = fmaf(wv.y, hx[c].y, d1);
                d2 = fmaf(wv.z, hx[c].z, d2); d3 = fmaf(wv.w, hx[c].w, d3);
            }
            float acc = (d0 + d1) + (d2 + d3);
            acc += __shfl_xor_sync(FULL, acc, 1);
            acc += __shfl_xor_sync(FULL, acc, 2);
            acc += __shfl_xor_sync(FULL, acc, 4);
            if (oct == 0)
                bcast_arrive(rb, (OFF_HD + rank * 16 + j) * 4, tanha(acc + pre_r), B_D);
        }

        // ======== stage A (step t+1) hh-half — hides wait_D ========
        a0 = 0; a1 = 0; a2 = 0; a3 = 0;
        if (t < STEPS - 1) {
            const float4* hv = (const float4*)(h0w + cs * 64);  // h0(t)
#pragma unroll
            for (int k = 0; k < 16; k++) { float4 wv = W0[((3 + k) << 7) + tid]; FMA4(wv, hv[k]); }
        }
        mbar_wait(sbase + B_D, ph);             // hD full ready

        // ======== stages E/F/G: redundant local (reg-resident weights) ========
        {
            const float4* xv = (const float4*)hD;
            float e0 = 0, e1 = 0, e2 = 0, e3 = 0;
#pragma unroll
            for (int k = 0; k < 32; k++) {
                e0 = fmaf(wreg[k].x, xv[k].x, e0); e1 = fmaf(wreg[k].y, xv[k].y, e1);
                e2 = fmaf(wreg[k].z, xv[k].z, e2); e3 = fmaf(wreg[k].w, xv[k].w, e3);
            }
            hidE[tid] = fmaxf(((e0 + e1) + (e2 + e3)) + bhhf[tid], 0.f);
        }
        __syncthreads();
        {
            const float4* xv = (const float4*)hidE;
            float e0 = 0, e1 = 0, e2 = 0, e3 = 0;
#pragma unroll
            for (int k = 0; k < 32; k++) {
                e0 = fmaf(wreg[k].x, xv[k].x, e0); e1 = fmaf(wreg[k].y, xv[k].y, e1);
                e2 = fmaf(wreg[k].z, xv[k].z, e2); e3 = fmaf(wreg[k].w, xv[k].w, e3);
            }
            hidF[tid] = fmaxf(((e0 + e1) + (e2 + e3)) + bhhf[tid], 0.f);
        }
        __syncthreads();
        if (tid < 96) {
            const float4* xv = (const float4*)(hidF + oct * 16);
            float e0 = 0, e1 = 0, e2 = 0, e3 = 0;
#pragma unroll
            for (int c = 0; c < 4; c++) {
                e0 = fmaf(gwreg[c].x, xv[c].x, e0); e1 = fmaf(gwreg[c].y, xv[c].y, e1);
                e2 = fmaf(gwreg[c].z, xv[c].z, e2); e3 = fmaf(gwreg[c].w, xv[c].w, e3);
            }
            float acc = (e0 + e1) + (e2 + e3);
            acc += __shfl_xor_sync(FULL, acc, 1);
            acc += __shfl_xor_sync(FULL, acc, 2);
            acc += __shfl_xor_sync(FULL, acc, 4);
            if (oct == 0) {
                int r = tid >> 3;  // 0..11
                float ov = sigm(acc + bh2o[r]);
                obuf[r] = ov;
                if (rank == 0) dout[(size_t)t * ODIM + r] = ov;
            }
        }
        __syncthreads();

        // ======== stage A (step t+1) rest: obuf part + gates + bcast ========
        if (t < STEPS - 1) {
            if (cs == 0) {
                const float4* ob4 = (const float4*)obuf;
#pragma unroll
                for (int k = 0; k < 3; k++) { float4 wv = W0[(k << 7) + tid]; FMA4(wv, ob4[k]); }
            }
            float acc = (a0 + a1) + (a2 + a3);
            acc += __shfl_xor_sync(FULL, acc, 1);
            acc += bA;
            gate_tail(acc, cA, rb, (OFF_H0 + q * 128 + rank * 16 + j) * 4, B_A, oct, base);
        }
    }

    // ---------------- final hN / cN ----------------
    if (out_size >= STEPS * ODIM + 6 * HDIM) {
        const int fb = STEPS * ODIM;  // 49152
        if (rank == 0) {
            dout[fb + tid]       = h0b[128 + tid];  // final parity = 1
            dout[fb + 128 + tid] = h1b[128 + tid];
            dout[fb + 256 + tid] = h2b[128 + tid];
        }
        if (oct == 0) {
            dout[fb + 384 + 0 * 128 + rank * 16 + j] = cA;
            dout[fb + 384 + 1 * 128 + rank * 16 + j] = cB;
            dout[fb + 384 + 2 * 128 + rank * 16 + j] = cC;
        }
    }
}

// =====================================================================
// launch
// =====================================================================
extern "C" void kernel_launch(void* const* d_in, const int* in_sizes, int n_in,
                              void* d_out, int out_size) {
    const float* inputs = (const float*)d_in[0];
    const float* out0   = (const float*)d_in[1];
    const float* h0in   = (const float*)d_in[2];
    const float* c0in   = (const float*)d_in[3];
    const float* W_s2i  = (const float*)d_in[4];
    const float* b_s2i  = (const float*)d_in[5];
    const float* W_i2h  = (const float*)d_in[6];
    const float* b_i2h  = (const float*)d_in[7];
    const float* W_h2h  = (const float*)d_in[8];
    const float* b_h2h  = (const float*)d_in[9];
    const float* W_h2o  = (const float*)d_in[10];
    const float* b_h2o  = (const float*)d_in[11];
    const float* Wih0   = (const float*)d_in[12];
    const float* Whh0   = (const float*)d_in[13];
    const float* bih0   = (const float*)d_in[14];
    const float* bhh0   = (const float*)d_in[15];
    const float* Wih1   = (const float*)d_in[16];
    const float* Whh1   = (const float*)d_in[17];
    const float* bih1   = (const float*)d_in[18];
    const float* bhh1   = (const float*)d_in[19];
    const float* Wih2   = (const float*)d_in[20];
    const float* Whh2   = (const float*)d_in[21];
    const float* bih2   = (const float*)d_in[22];
    const float* bhh2   = (const float*)d_in[23];
    float* dout = (float*)d_out;

    cudaFuncSetAttribute(k_scan, cudaFuncAttributeMaxDynamicSharedMemorySize, SMEM_BYTES);

    k_cf<<<1, 128>>>(b_s2i, W_i2h, b_i2h);
    k_mt<<<dim3(DATA / 256, HDIM / 16), 256>>>(W_s2i, W_i2h);
    k_pre<<<STEPS / 16, 256>>>(inputs);
    k_scan<<<NCTA, TPB, SMEM_BYTES>>>(out0, h0in, c0in,
                                      W_i2h, W_h2h, b_h2h, W_h2o, b_h2o,
                                      Wih0, Whh0, bih0, bhh0,
                                      Wih1, Whh1, bih1, bhh1,
                                      Wih2, Whh2, bih2, bhh2,
                                      dout, out_size);
}